// round 10
// baseline (speedup 1.0000x reference)
#include <cuda_runtime.h>
#include <cuda_fp16.h>
#include <cstdint>

#define C      128
#define KNBR   27
#define TM     128
#define NMAX   300000
#define N_WMAT 191                    // 162 W_res + 27 W_out + Wf1 + Wf2
#define CAP    16384                  // per-k pair list capacity (expect ~5.4k)
#define NSEG   27
#define SCR_ROWS (1 << 21)            // scratch rows (expect ~141k)
#define NBMAX  512
#define PSP    5                      // persistent CTAs per k (sparse): 135 CTAs
#define GDMAX  148                    // persistent CTAs (dense), 1/SM

#define PITCH  80                     // A: bytes per 32-half row (16B padded)
#define PLANE  10240                  // A: 128 * PITCH (lo-plane offset)
#define ASZ    20480                  // A stage: hi+lo planes
#define BPITCH 528                    // B-full: 512B row + 16B pad (bank shift)
#define BFULL  67584                  // 128 * BPITCH
#define DN2_SMEM (BFULL + 3 * ASZ)          // 129024
#define SP2_SMEM (BFULL + 2048 + 3 * ASZ)   // 131072

// activations: per row 256 halfs, per 32-ci chunk: [hi32 | lo32] x4
__device__ __half g_actA[(size_t)NMAX * 256];
__device__ __half g_actB[(size_t)NMAX * 256];
// weights: per mat 32768 halfs, [co][ci chunks interleaved hi/lo]
__device__ __half g_Wt[(size_t)N_WMAT * 32768];
// sparse-pair machinery (m-sorted scratch slots, scan-based — no atomics)
__device__ float         g_scr[(size_t)SCR_ROWS * C];
__device__ unsigned      g_cnt[NSEG];
__device__ int           g_pairg[NSEG * CAP];   // source row per pair
__device__ int           g_slot[NSEG * CAP];    // scratch row per pair
__device__ int           g_mbase[NMAX];         // first scratch row of m
__device__ unsigned char g_mcnt[NMAX];          // valid non-self count of m
__device__ int           g_bsum[NBMAX];
__device__ int           g_boff[NBMAX];
__device__ int           g_kcnt[NSEG * NBMAX];  // [k][block] counts (transposed)
__device__ int           g_kbase[NSEG * NBMAX]; // [k][block] exclusive scan

// ---------------------------------------------------------------------------
static __device__ __forceinline__ void cp_async16_cg(uint32_t dst, const void* src, bool pred) {
    int sz = pred ? 16 : 0;
    asm volatile("cp.async.cg.shared.global [%0], [%1], 16, %2;"
                 :: "r"(dst), "l"(src), "r"(sz) : "memory");
}
static __device__ __forceinline__ void cp_async16_ca(uint32_t dst, const void* src, bool pred) {
    int sz = pred ? 16 : 0;
    asm volatile("cp.async.ca.shared.global [%0], [%1], 16, %2;"
                 :: "r"(dst), "l"(src), "r"(sz) : "memory");
}
#define CP_COMMIT() asm volatile("cp.async.commit_group;" ::: "memory")
template <int N> static __device__ __forceinline__ void cp_wait() {
    asm volatile("cp.async.wait_group %0;" :: "n"(N) : "memory");
}
static __device__ __forceinline__ uint32_t smem_u32(const void* p) {
    uint32_t a;
    asm("{ .reg .u64 t; cvta.to.shared.u64 t, %1; cvt.u32.u64 %0, t; }"
        : "=r"(a) : "l"(p));
    return a;
}
static __device__ __forceinline__ void mma_f16(float* c, const uint32_t* a,
                                               uint32_t b0, uint32_t b1) {
    asm volatile(
        "mma.sync.aligned.m16n8k16.row.col.f32.f16.f16.f32 "
        "{%0,%1,%2,%3}, {%4,%5,%6,%7}, {%8,%9}, {%0,%1,%2,%3};"
        : "+f"(c[0]), "+f"(c[1]), "+f"(c[2]), "+f"(c[3])
        : "r"(a[0]), "r"(a[1]), "r"(a[2]), "r"(a[3]), "r"(b0), "r"(b1));
}
static __device__ __forceinline__ void ldsm4(uint32_t* r, uint32_t addr) {
    asm volatile("ldmatrix.sync.aligned.m8n8.x4.shared.b16 {%0,%1,%2,%3}, [%4];"
                 : "=r"(r[0]), "=r"(r[1]), "=r"(r[2]), "=r"(r[3]) : "r"(addr));
}
static __device__ __forceinline__ void split2(float v, __half& h, __half& l) {
    h = __float2half_rn(v);
    l = __float2half_rn(v - __half2float(h));
}

// ---------------------------------------------------------------------------
// 3-term inner loop for one 32-ci chunk.
// A in stage layout (PITCH, lo at +PLANE); B resident (BPITCH, chunk cc at
// +cc*128, lo at +64).
// ---------------------------------------------------------------------------
static __device__ __forceinline__ void gemm_chunk_p(uint32_t smA, uint32_t smB, int cc,
                                                    int rg, int cg, int lane,
                                                    float acc[2][8][4])
{
    const int arow = lane & 15, asel = (lane >> 4) & 1;
    const int brow = (lane & 7) + ((lane >> 4) & 1) * 8;
    const int bsel = (lane >> 3) & 1;
#pragma unroll
    for (int ks = 0; ks < 2; ks++) {
        uint32_t aaddr = smA + (rg * 32 + arow) * PITCH + ks * 32 + asel * 16;
        uint32_t baddr = smB + (cg * 64 + brow) * BPITCH + cc * 128 + ks * 32 + bsel * 16;
        uint32_t ah[2][4], al[2][4], bf[4][4];
        ldsm4(ah[0], aaddr);
        ldsm4(ah[1], aaddr + 16 * PITCH);
        ldsm4(al[0], aaddr + PLANE);
        ldsm4(al[1], aaddr + PLANE + 16 * PITCH);
#pragma unroll
        for (int t = 0; t < 4; t++) ldsm4(bf[t], baddr + t * 16 * BPITCH);
#pragma unroll
        for (int t = 0; t < 4; t++)
#pragma unroll
            for (int h = 0; h < 2; h++) {
                int nt = t * 2 + h;
                mma_f16(acc[0][nt], ah[0], bf[t][2 * h], bf[t][2 * h + 1]);
                mma_f16(acc[1][nt], ah[1], bf[t][2 * h], bf[t][2 * h + 1]);
                mma_f16(acc[0][nt], al[0], bf[t][2 * h], bf[t][2 * h + 1]);
                mma_f16(acc[1][nt], al[1], bf[t][2 * h], bf[t][2 * h + 1]);
            }
#pragma unroll
        for (int t = 0; t < 4; t++) ldsm4(bf[t], baddr + 64 + t * 16 * BPITCH);
#pragma unroll
        for (int t = 0; t < 4; t++)
#pragma unroll
            for (int h = 0; h < 2; h++) {
                int nt = t * 2 + h;
                mma_f16(acc[0][nt], ah[0], bf[t][2 * h], bf[t][2 * h + 1]);
                mma_f16(acc[1][nt], ah[1], bf[t][2 * h], bf[t][2 * h + 1]);
            }
    }
}

// ---------------------------------------------------------------------------
// Weight prepass: transpose [ci][co] -> [co][ci], split fp16 hi/lo interleaved
// ---------------------------------------------------------------------------
__global__ void prep_w_kernel(const float* __restrict__ W_res,
                              const float* __restrict__ W_out,
                              const float* __restrict__ Wf1,
                              const float* __restrict__ Wf2)
{
    __shared__ float t[32][33];
    const int b = blockIdx.x;
    const float* src;
    if (b < 162)       src = W_res + (size_t)b * C * C;
    else if (b < 189)  src = W_out + (size_t)(b - 162) * C * C;
    else if (b == 189) src = Wf1;
    else               src = Wf2;
    __half* dst = g_Wt + ((size_t)b << 15);

    const int j = threadIdx.x & 31, i0 = threadIdx.x >> 5;
    for (int tile = 0; tile < 16; tile++) {
        const int tr = tile >> 2, tc = tile & 3;
        __syncthreads();
#pragma unroll
        for (int p = 0; p < 4; p++)
            t[i0 + p * 8][j] = src[(tr * 32 + i0 + p * 8) * C + tc * 32 + j];
        __syncthreads();
#pragma unroll
        for (int p = 0; p < 4; p++) {
            int co = tc * 32 + i0 + p * 8;
            float w = t[j][i0 + p * 8];
            __half h, l; split2(w, h, l);
            size_t o = (size_t)co * 256 + tr * 64 + j;
            dst[o] = h;
            dst[o + 32] = l;
        }
    }
}

// ---------------------------------------------------------------------------
// Pair prepass (atomic-free)
// ---------------------------------------------------------------------------
__global__ __launch_bounds__(1024)
void count_scan_kernel(const int* __restrict__ nbr, int n)
{
    __shared__ int wsum[32];
    __shared__ int s_wk[NSEG * 32];
    const int tid = threadIdx.x, lane = tid & 31, wid = tid >> 5;
    const int m = blockIdx.x * 1024 + tid;

    unsigned valid27 = 0;
    if (m < n) {
        const int* np = nbr + (size_t)m * KNBR;
#pragma unroll
        for (int k = 0; k < KNBR; k++)
            if (k != 13 && np[k] >= 0) valid27 |= (1u << k);
    }
    int cnt = __popc(valid27);

#pragma unroll
    for (int k = 0; k < KNBR; k++) {
        if (k == 13) continue;
        unsigned ball = __ballot_sync(0xFFFFFFFFu, (valid27 >> k) & 1u);
        if (lane == 0) s_wk[k * 32 + wid] = __popc(ball);
    }

    int v = cnt;
#pragma unroll
    for (int o = 1; o < 32; o <<= 1) {
        int u = __shfl_up_sync(0xFFFFFFFFu, v, o);
        if (lane >= o) v += u;
    }
    if (lane == 31) wsum[wid] = v;
    __syncthreads();
    if (wid == 0) {
        int w = wsum[lane], iv = w;
#pragma unroll
        for (int o = 1; o < 32; o <<= 1) {
            int u = __shfl_up_sync(0xFFFFFFFFu, iv, o);
            if (lane >= o) iv += u;
        }
        wsum[lane] = iv - w;
    }
    __syncthreads();
    int pre = wsum[wid] + v - cnt;
    if (m < n) {
        g_mcnt[m] = (unsigned char)cnt;
        g_mbase[m] = pre;
    }
    if (tid == 1023) g_bsum[blockIdx.x] = pre + cnt;

    if (wid < NSEG && wid != 13) {
        int t = s_wk[wid * 32 + lane];
#pragma unroll
        for (int o = 16; o > 0; o >>= 1) t += __shfl_down_sync(0xFFFFFFFFu, t, o);
        if (lane == 0) g_kcnt[wid * NBMAX + blockIdx.x] = t;
    }
}

__global__ __launch_bounds__(1024)
void scan_bsum_kernel(int nb)
{
    __shared__ int s[512];
    const int tid = threadIdx.x, lane = tid & 31, w = tid >> 5;
    int v = 0;
    if (tid < 512) {
        v = (tid < nb) ? g_bsum[tid] : 0;
        s[tid] = v;
    }
    __syncthreads();
    for (int off = 1; off < 512; off <<= 1) {
        int u = (tid < 512 && tid >= off) ? s[tid - off] : 0;
        __syncthreads();
        if (tid < 512) s[tid] += u;
        __syncthreads();
    }
    if (tid < 512 && tid < nb) g_boff[tid] = s[tid] - v;

    // per-k exclusive scan over blocks — one warp per k, shuffle scan
    if (w < NSEG && w != 13) {
        int run = 0;
        for (int b0 = 0; b0 < nb; b0 += 32) {
            int b = b0 + lane;
            int x = (b < nb) ? g_kcnt[w * NBMAX + b] : 0;
            int inc = x;
#pragma unroll
            for (int o = 1; o < 32; o <<= 1) {
                int u = __shfl_up_sync(0xFFFFFFFFu, inc, o);
                if (lane >= o) inc += u;
            }
            if (b < nb) g_kbase[w * NBMAX + b] = run + inc - x;
            run += __shfl_sync(0xFFFFFFFFu, inc, 31);
        }
        if (lane == 0) g_cnt[w] = (unsigned)run;
    }
    if (tid == 0) g_cnt[13] = 0;
}

__global__ __launch_bounds__(1024)
void emit_pairs_kernel(const int* __restrict__ nbr, int n)
{
    __shared__ int s_wk[NSEG * 32];
    __shared__ int s_kb[NSEG];
    const int tid = threadIdx.x, lane = tid & 31, wid = tid >> 5;
    const int m = blockIdx.x * 1024 + tid;

    unsigned valid27 = 0;
    if (m < n) {
        const int* np = nbr + (size_t)m * KNBR;
#pragma unroll
        for (int k = 0; k < KNBR; k++)
            if (k != 13 && np[k] >= 0) valid27 |= (1u << k);
    }
#pragma unroll
    for (int k = 0; k < KNBR; k++) {
        if (k == 13) continue;
        unsigned ball = __ballot_sync(0xFFFFFFFFu, (valid27 >> k) & 1u);
        if (lane == 0) s_wk[k * 32 + wid] = __popc(ball);
    }
    if (tid < NSEG) s_kb[tid] = (tid != 13) ? g_kbase[tid * NBMAX + blockIdx.x] : 0;
    __syncthreads();

    if (wid < NSEG && wid != 13) {
        int v = s_wk[wid * 32 + lane], orig = v;
#pragma unroll
        for (int o = 1; o < 32; o <<= 1) {
            int u = __shfl_up_sync(0xFFFFFFFFu, v, o);
            if (lane >= o) v += u;
        }
        s_wk[wid * 32 + lane] = v - orig;
    }
    __syncthreads();

    int base = 0;
    if (m < n) base = g_boff[m >> 10] + g_mbase[m];
    const unsigned lt = (1u << lane) - 1u;
    int j = 0;
#pragma unroll
    for (int k = 0; k < KNBR; k++) {
        if (k == 13) continue;
        bool valid = (valid27 >> k) & 1u;
        unsigned ball = __ballot_sync(0xFFFFFFFFu, valid);
        if (valid) {
            int pos = s_kb[k] + s_wk[k * 32 + wid] + __popc(ball & lt);
            if (pos < CAP && base + j < SCR_ROWS) {
                g_pairg[k * CAP + pos] = nbr[(size_t)m * KNBR + k];
                g_slot[k * CAP + pos] = base + j;
            }
            j++;
        }
    }
    if (m < n) g_mbase[m] = base;
}

// ---------------------------------------------------------------------------
// Phase 1 (persistent, B-stationary, 3-stage single-barrier pipeline):
// per-k pair GEMM -> fp32 scratch rows (m-sorted slots)
// ---------------------------------------------------------------------------
__global__ __launch_bounds__(256, 1)
void sparse_mma_p(const __half* __restrict__ in, const __half* __restrict__ WtLayer)
{
    const int k = blockIdx.x % NSEG;
    const int c = blockIdx.x / NSEG;
    unsigned cnt = g_cnt[k];
    if (cnt > CAP) cnt = CAP;
    const int ntk = (int)((cnt + TM - 1) / TM);
    const int mytiles = (ntk - c + PSP - 1) / PSP;
    if (mytiles <= 0) return;
    const int total = 4 * mytiles;

    extern __shared__ char smem[];
    const uint32_t sb = smem_u32(smem);
    const int tid = threadIdx.x, wid = tid >> 5, lane = tid & 31;
    const int lr = lane >> 2, lc = lane & 3;
    const int rg = wid & 3, cg = wid >> 2;

    int (*s_g)[TM] = (int(*)[TM])(smem + BFULL);
    int (*s_s)[TM] = (int(*)[TM])(smem + BFULL + 1024);
    const uint32_t ABASE = sb + BFULL + 2048;
    const __half* Wk = WtLayer + ((size_t)k << 15);

    auto load_idx = [&](int tl) {
        if (tid < TM) {
            int p = (c + tl * PSP) * TM + tid;
            int buf = tl & 1;
            s_g[buf][tid] = (p < (int)cnt) ? g_pairg[k * CAP + p] : -1;
            s_s[buf][tid] = (p < (int)cnt) ? g_slot[k * CAP + p] : -1;
        }
    };

    auto produce = [&](int q) {
        const int tl = q >> 2, cc = q & 3, buf = tl & 1;
        const uint32_t stA = ABASE + (q % 3) * ASZ;
#pragma unroll
        for (int i = 0; i < 4; i++) {
            int u = tid + 256 * i;
            int r = u >> 3, qq = u & 7;
            int idx = s_g[buf][r];
            const __half* src = in + (size_t)(idx < 0 ? 0 : idx) * 256 + cc * 64 + qq * 8;
            uint32_t dst = stA + ((qq & 4) ? PLANE : 0) + r * PITCH + (qq & 3) * 16;
            cp_async16_ca(dst, src, idx >= 0);
        }
        if (q == 0) {
#pragma unroll
            for (int i = 0; i < 16; i++) {
                int u = tid + 256 * i;
                int r = u >> 5, qq = u & 31;
                cp_async16_cg(sb + r * BPITCH + qq * 16, Wk + (size_t)r * 256 + qq * 8, true);
            }
        }
        CP_COMMIT();
    };

    float acc[2][8][4];
#pragma unroll
    for (int mt = 0; mt < 2; mt++)
#pragma unroll
        for (int nt = 0; nt < 8; nt++)
#pragma unroll
            for (int j = 0; j < 4; j++) acc[mt][nt][j] = 0.f;

    load_idx(0);
    __syncthreads();
    produce(0);
    produce(1);

    for (int jj = 0; jj < total; jj++) {
        if (jj == total - 1) cp_wait<0>(); else cp_wait<1>();
        __syncthreads();
        if (jj + 2 < total) produce(jj + 2);
        gemm_chunk_p(ABASE + (jj % 3) * ASZ, sb, jj & 3, rg, cg, lane, acc);
        if ((jj & 3) == 1 && (jj >> 2) + 1 < mytiles) load_idx((jj >> 2) + 1);

        if ((jj & 3) == 3) {
            const int tl = jj >> 2, buf = tl & 1;
            const int base = (c + tl * PSP) * TM;
#pragma unroll
            for (int mt = 0; mt < 2; mt++) {
#pragma unroll
                for (int hf = 0; hf < 2; hf++) {
                    int pr = rg * 32 + mt * 16 + hf * 8 + lr;
                    if (base + pr < (int)cnt) {
                        int slot = s_s[buf][pr];
                        if (slot >= 0) {
                            float* op = g_scr + (size_t)slot * C + cg * 64 + lc * 2;
#pragma unroll
                            for (int nt = 0; nt < 8; nt++)
                                *(float2*)(op + nt * 8) =
                                    make_float2(acc[mt][nt][hf * 2 + 0],
                                                acc[mt][nt][hf * 2 + 1]);
                        }
                    }
                }
            }
#pragma unroll
            for (int mt = 0; mt < 2; mt++)
#pragma unroll
                for (int nt = 0; nt < 8; nt++)
#pragma unroll
                    for (int j = 0; j < 4; j++) acc[mt][nt][j] = 0.f;
        }
    }
}

// ---------------------------------------------------------------------------
// Phase 2 (persistent, B-stationary, 3-stage single-barrier pipeline):
// dense self-term GEMM + fused combine epilogue
// ---------------------------------------------------------------------------
__global__ __launch_bounds__(256, 1)
void dense_mma_p(const __half* __restrict__ in, __half* __restrict__ outAct,
                 const __half* __restrict__ Wk, const float* __restrict__ bias,
                 const __half* __restrict__ resid, int relu, int sparse,
                 int n, int ntiles)
{
    const int mytiles = (ntiles - (int)blockIdx.x + (int)gridDim.x - 1) / (int)gridDim.x;
    if (mytiles <= 0) return;
    const int total = 4 * mytiles;

    extern __shared__ char smem[];
    const uint32_t sb = smem_u32(smem);
    const int tid = threadIdx.x, wid = tid >> 5, lane = tid & 31;
    const int lr = lane >> 2, lc = lane & 3;
    const int rg = wid & 3, cg = wid >> 2;
    const uint32_t ABASE = sb + BFULL;

    auto produce = [&](int q) {
        const int tl = q >> 2, cc = q & 3;
        const int row0 = ((int)blockIdx.x + tl * (int)gridDim.x) * TM;
        const uint32_t stA = ABASE + (q % 3) * ASZ;
#pragma unroll
        for (int i = 0; i < 4; i++) {
            int u = tid + 256 * i;
            int r = u >> 3, qq = u & 7;
            int idx = (row0 + r < n) ? row0 + r : -1;
            const __half* src = in + (size_t)(idx < 0 ? 0 : idx) * 256 + cc * 64 + qq * 8;
            uint32_t dst = stA + ((qq & 4) ? PLANE : 0) + r * PITCH + (qq & 3) * 16;
            cp_async16_cg(dst, src, idx >= 0);
        }
        if (q == 0) {
#pragma unroll
            for (int i = 0; i < 16; i++) {
                int u = tid + 256 * i;
                int r = u >> 5, qq = u & 31;
                cp_async16_cg(sb + r * BPITCH + qq * 16, Wk + (size_t)r * 256 + qq * 8, true);
            }
        }
        CP_COMMIT();
    };

    float acc[2][8][4];
#pragma unroll
    for (int mt = 0; mt < 2; mt++)
#pragma unroll
        for (int nt = 0; nt < 8; nt++)
#pragma unroll
            for (int j = 0; j < 4; j++) acc[mt][nt][j] = 0.f;

    float2 bv[8];
#pragma unroll
    for (int nt = 0; nt < 8; nt++)
        bv[nt] = *(const float2*)(bias + cg * 64 + nt * 8 + lc * 2);

    produce(0);
    produce(1);

    for (int jj = 0; jj < total; jj++) {
        if (jj == total - 1) cp_wait<0>(); else cp_wait<1>();
        __syncthreads();
        if (jj + 2 < total) produce(jj + 2);
        gemm_chunk_p(ABASE + (jj % 3) * ASZ, sb, jj & 3, rg, cg, lane, acc);

        if ((jj & 3) == 3) {
            const int row0 = ((int)blockIdx.x + (jj >> 2) * (int)gridDim.x) * TM;
#pragma unroll
            for (int mt = 0; mt < 2; mt++) {
#pragma unroll
                for (int hf = 0; hf < 2; hf++) {
                    int row = row0 + rg * 32 + mt * 16 + hf * 8 + lr;
                    if (row >= n) continue;
                    float v[8][2];
#pragma unroll
                    for (int nt = 0; nt < 8; nt++) {
                        v[nt][0] = acc[mt][nt][hf * 2 + 0] + bv[nt].x;
                        v[nt][1] = acc[mt][nt][hf * 2 + 1] + bv[nt].y;
                    }
                    if (sparse) {
                        int basem = g_mbase[row];
                        int mc = g_mcnt[row];
                        const float* sp = g_scr + (size_t)basem * C + cg * 64 + lc * 2;
                        for (int j = 0; j < mc; j++) {
#pragma unroll
                            for (int nt = 0; nt < 8; nt++) {
                                float2 sv = *(const float2*)(sp + nt * 8);
                                v[nt][0] += sv.x;
                                v[nt][1] += sv.y;
                            }
                            sp += C;
                        }
                    }
#pragma unroll
                    for (int nt = 0; nt < 8; nt++) {
                        int col = cg * 64 + nt * 8 + lc * 2;
                        size_t o = (size_t)row * 256 + (col >> 5) * 64 + (col & 31);
                        float v0 = v[nt][0], v1 = v[nt][1];
                        if (resid) {
                            __half2 rh = *(const __half2*)(resid + o);
                            __half2 rl = *(const __half2*)(resid + o + 32);
                            v0 += __half2float(__low2half(rh)) + __half2float(__low2half(rl));
                            v1 += __half2float(__high2half(rh)) + __half2float(__high2half(rl));
                        }
                        if (relu) { v0 = fmaxf(v0, 0.f); v1 = fmaxf(v1, 0.f); }
                        __half h0, l0, h1, l1;
                        split2(v0, h0, l0);
                        split2(v1, h1, l1);
                        *(__half2*)(outAct + o)      = __halves2half2(h0, h1);
                        *(__half2*)(outAct + o + 32) = __halves2half2(l0, l1);
                    }
                }
            }
#pragma unroll
            for (int mt = 0; mt < 2; mt++)
#pragma unroll
                for (int nt = 0; nt < 8; nt++)
#pragma unroll
                    for (int j = 0; j < 4; j++) acc[mt][nt][j] = 0.f;
        }
    }
}

// ---------------------------------------------------------------------------
// Input layer (Cin = 1), sparsity-compacted
// ---------------------------------------------------------------------------
__global__ __launch_bounds__(256)
void layer_in_kernel(const float* __restrict__ x, __half* __restrict__ outAct,
                     const float* __restrict__ Win, const float* __restrict__ bin,
                     const int* __restrict__ nbr, int n)
{
    __shared__ float ws[KNBR][C];
    __shared__ float s_val[TM][28];
    __shared__ unsigned char s_kk[TM][28];
    __shared__ int s_cnt[TM];
    const int tid  = threadIdx.x;
    const int row0 = blockIdx.x * TM;

    for (int f = tid; f < KNBR * C; f += 256) ws[f / C][f & (C - 1)] = Win[f];
    if (tid < TM) {
        int row = row0 + tid;
        int j = 0;
        if (row < n) {
            const int* np = nbr + (size_t)row * KNBR;
#pragma unroll
            for (int k = 0; k < KNBR; k++) {
                int g = np[k];
                if (g >= 0) {
                    s_kk[tid][j] = (unsigned char)k;
                    s_val[tid][j] = x[g];
                    j++;
                }
            }
        }
        s_cnt[tid] = j;
    }
    __syncthreads();

    const int c  = tid & (C - 1);
    const int rg = tid >> 7;
    const float b = bin[c];
    const size_t co = (size_t)(c >> 5) * 64 + (c & 31);
    for (int r = rg; r < TM; r += 2) {
        int row = row0 + r;
        if (row >= n) continue;
        float acc = b;
        int cnt = s_cnt[r];
        for (int j = 0; j < cnt; j++)
            acc += s_val[r][j] * ws[s_kk[r][j]][c];
        acc = fmaxf(acc, 0.f);
        __half h, l; split2(acc, h, l);
        outAct[(size_t)row * 256 + co] = h;
        outAct[(size_t)row * 256 + co + 32] = l;
    }
}

// ---------------------------------------------------------------------------
// Final layer
// ---------------------------------------------------------------------------
__global__ __launch_bounds__(256)
void final_kernel(const __half* __restrict__ act, float* __restrict__ out,
                  const float* __restrict__ Wf3, const float* __restrict__ bf3, int n)
{
    __shared__ float hs[64][C + 1];
    __shared__ float wl[C * 3];
    __shared__ float bl[3];
    const int tid  = threadIdx.x;
    const int row0 = blockIdx.x * 64;

    for (int flat = tid; flat < 64 * C / 2; flat += 256) {
        int r = flat >> 6, q = flat & 63;
        int row = row0 + r;
        int col = (q >> 4) * 32 + (q & 15) * 2;
        float v0 = 0.f, v1 = 0.f;
        if (row < n) {
            size_t o = (size_t)row * 256 + (col >> 5) * 64 + (col & 31);
            __half2 rh = *(const __half2*)(act + o);
            __half2 rl = *(const __half2*)(act + o + 32);
            v0 = __half2float(__low2half(rh)) + __half2float(__low2half(rl));
            v1 = __half2float(__high2half(rh)) + __half2float(__high2half(rl));
        }
        hs[r][col] = v0;
        hs[r][col + 1] = v1;
    }
    for (int flat = tid; flat < C * 3; flat += 256) wl[flat] = Wf3[flat];
    if (tid < 3) bl[tid] = bf3[tid];
    __syncthreads();

    if (tid < 192) {
        int r = tid / 3, j = tid % 3;
        int row = row0 + r;
        if (row < n) {
            float acc = bl[j];
#pragma unroll 4
            for (int ci = 0; ci < C; ci++) acc += hs[r][ci] * wl[ci * 3 + j];
            out[(size_t)row * 3 + j] = acc;
        }
    }
}

// ---------------------------------------------------------------------------
extern "C" void kernel_launch(void* const* d_in, const int* in_sizes, int n_in,
                              void* d_out, int out_size)
{
    const float* x_feat = (const float*)d_in[0];
    const float* W_in   = (const float*)d_in[1];
    const float* b_in   = (const float*)d_in[2];
    const float* W_res  = (const float*)d_in[3];
    const float* b_res  = (const float*)d_in[4];
    const float* W_out  = (const float*)d_in[5];
    const float* b_out  = (const float*)d_in[6];
    const float* Wf1    = (const float*)d_in[7];
    const float* bf1    = (const float*)d_in[8];
    const float* Wf2    = (const float*)d_in[9];
    const float* bf2    = (const float*)d_in[10];
    const float* Wf3    = (const float*)d_in[11];
    const float* bf3    = (const float*)d_in[12];
    const int*   nbr    = (const int*)d_in[13];
    float* out = (float*)d_out;

    const int n = in_sizes[0];

    __half *actA, *actB, *Wt;
    cudaGetSymbolAddress((void**)&actA, g_actA);
    cudaGetSymbolAddress((void**)&actB, g_actB);
    cudaGetSymbolAddress((void**)&Wt, g_Wt);

    cudaFuncSetAttribute(sparse_mma_p, cudaFuncAttributeMaxDynamicSharedMemorySize, SP2_SMEM);
    cudaFuncSetAttribute(dense_mma_p, cudaFuncAttributeMaxDynamicSharedMemorySize, DN2_SMEM);

    const int ntiles = (n + TM - 1) / TM;
    const int gridM  = ntiles;
    const int gridD  = ntiles < GDMAX ? ntiles : GDMAX;
    const int gridS  = NSEG * PSP;
    const int nb     = (n + 1023) / 1024;

    prep_w_kernel<<<N_WMAT, 256>>>(W_res, W_out, Wf1, Wf2);
    count_scan_kernel<<<nb, 1024>>>(nbr, n);
    scan_bsum_kernel<<<1, 1024>>>(nb);
    emit_pairs_kernel<<<nb, 1024>>>(nbr, n);

    layer_in_kernel<<<gridM, 256>>>(x_feat, actA, W_in, b_in, nbr, n);

    for (int i = 0; i < 3; i++) {
        const __half* W0 = Wt + ((size_t)((i * 2 + 0) * KNBR) << 15);
        const __half* W1 = Wt + ((size_t)((i * 2 + 1) * KNBR) << 15);
        const float* b0 = b_res + (size_t)(i * 2 + 0) * C;
        const float* b1 = b_res + (size_t)(i * 2 + 1) * C;
        sparse_mma_p<<<gridS, 256, SP2_SMEM>>>(actA, W0);
        dense_mma_p<<<gridD, 256, DN2_SMEM>>>(actA, actB, W0 + ((size_t)13 << 15),
                                              b0, nullptr, 1, 1, n, ntiles);
        sparse_mma_p<<<gridS, 256, SP2_SMEM>>>(actB, W1);
        dense_mma_p<<<gridD, 256, DN2_SMEM>>>(actB, actA, W1 + ((size_t)13 << 15),
                                              b1, actA, 0, 1, n, ntiles);
    }

    const __half* Wo = Wt + ((size_t)(6 * KNBR) << 15);
    sparse_mma_p<<<gridS, 256, SP2_SMEM>>>(actA, Wo);
    dense_mma_p<<<gridD, 256, DN2_SMEM>>>(actA, actB, Wo + ((size_t)13 << 15),
                                          b_out, nullptr, 0, 1, n, ntiles);

    dense_mma_p<<<gridD, 256, DN2_SMEM>>>(actB, actA, Wt + ((size_t)189 << 15),
                                          bf1, nullptr, 1, 0, n, ntiles);
    dense_mma_p<<<gridD, 256, DN2_SMEM>>>(actA, actB, Wt + ((size_t)190 << 15),
                                          bf2, nullptr, 1, 0, n, ntiles);

    final_kernel<<<(n + 63) / 64, 256>>>(actB, out, Wf3, bf3, n);
}

// round 11
// speedup vs baseline: 1.3050x; 1.3050x over previous
#include <cuda_runtime.h>
#include <cuda_fp16.h>
#include <cstdint>

#define C      128
#define KNBR   27
#define TM     128
#define NMAX   300000
#define N_WMAT 191                    // 162 W_res + 27 W_out + Wf1 + Wf2
#define CAP    16384                  // per-k pair list capacity (expect ~5.4k)
#define NSEG   27
#define SCR_ROWS (1 << 21)            // scratch rows (expect ~141k)
#define NBMAX  512
#define PSP    11                     // persistent CTAs per k (sparse): 297 CTAs
#define GDMAX  296                    // persistent CTAs (dense), 2/SM

#define PITCH  80                     // A: bytes per 32-half row (16B padded)
#define PLANE  10240                  // A: 128 * PITCH (lo-plane offset)
#define ASZ    20480                  // A stage: hi+lo planes
#define BPITCH 528                    // B-full: 512B row + 16B pad (bank shift)
#define BFULL  67584                  // 128 * BPITCH
#define DN2_SMEM (BFULL + 2 * ASZ)          // 108544 -> 2 CTA/SM
#define SP2_SMEM (BFULL + 2048 + 2 * ASZ)   // 110592 -> 2 CTA/SM

// activations: per row 256 halfs, per 32-ci chunk: [hi32 | lo32] x4
__device__ __half g_actA[(size_t)NMAX * 256];
__device__ __half g_actB[(size_t)NMAX * 256];
// weights: per mat 32768 halfs, [co][ci chunks interleaved hi/lo]
__device__ __half g_Wt[(size_t)N_WMAT * 32768];
// sparse-pair machinery (m-sorted scratch slots, scan-based — no atomics)
__device__ float         g_scr[(size_t)SCR_ROWS * C];
__device__ unsigned      g_cnt[NSEG];
__device__ int           g_pairg[NSEG * CAP];   // source row per pair
__device__ int           g_slot[NSEG * CAP];    // scratch row per pair
__device__ int           g_mbase[NMAX];         // first scratch row of m
__device__ unsigned char g_mcnt[NMAX];          // valid non-self count of m
__device__ int           g_bsum[NBMAX];
__device__ int           g_boff[NBMAX];
__device__ int           g_kcnt[NSEG * NBMAX];  // [k][block] counts (transposed)
__device__ int           g_kbase[NSEG * NBMAX]; // [k][block] exclusive scan

// ---------------------------------------------------------------------------
static __device__ __forceinline__ void cp_async16_cg(uint32_t dst, const void* src, bool pred) {
    int sz = pred ? 16 : 0;
    asm volatile("cp.async.cg.shared.global [%0], [%1], 16, %2;"
                 :: "r"(dst), "l"(src), "r"(sz) : "memory");
}
static __device__ __forceinline__ void cp_async16_ca(uint32_t dst, const void* src, bool pred) {
    int sz = pred ? 16 : 0;
    asm volatile("cp.async.ca.shared.global [%0], [%1], 16, %2;"
                 :: "r"(dst), "l"(src), "r"(sz) : "memory");
}
#define CP_COMMIT() asm volatile("cp.async.commit_group;" ::: "memory")
template <int N> static __device__ __forceinline__ void cp_wait() {
    asm volatile("cp.async.wait_group %0;" :: "n"(N) : "memory");
}
static __device__ __forceinline__ uint32_t smem_u32(const void* p) {
    uint32_t a;
    asm("{ .reg .u64 t; cvta.to.shared.u64 t, %1; cvt.u32.u64 %0, t; }"
        : "=r"(a) : "l"(p));
    return a;
}
static __device__ __forceinline__ void mma_f16(float* c, const uint32_t* a,
                                               uint32_t b0, uint32_t b1) {
    asm volatile(
        "mma.sync.aligned.m16n8k16.row.col.f32.f16.f16.f32 "
        "{%0,%1,%2,%3}, {%4,%5,%6,%7}, {%8,%9}, {%0,%1,%2,%3};"
        : "+f"(c[0]), "+f"(c[1]), "+f"(c[2]), "+f"(c[3])
        : "r"(a[0]), "r"(a[1]), "r"(a[2]), "r"(a[3]), "r"(b0), "r"(b1));
}
static __device__ __forceinline__ void ldsm4(uint32_t* r, uint32_t addr) {
    asm volatile("ldmatrix.sync.aligned.m8n8.x4.shared.b16 {%0,%1,%2,%3}, [%4];"
                 : "=r"(r[0]), "=r"(r[1]), "=r"(r[2]), "=r"(r[3]) : "r"(addr));
}
static __device__ __forceinline__ void split2(float v, __half& h, __half& l) {
    h = __float2half_rn(v);
    l = __float2half_rn(v - __half2float(h));
}

// ---------------------------------------------------------------------------
// 3-term inner loop for one 32-ci chunk.
// A in stage layout (PITCH, lo at +PLANE); B resident (BPITCH, chunk cc at
// +cc*128, lo at +64).
// ---------------------------------------------------------------------------
static __device__ __forceinline__ void gemm_chunk_p(uint32_t smA, uint32_t smB, int cc,
                                                    int rg, int cg, int lane,
                                                    float acc[2][8][4])
{
    const int arow = lane & 15, asel = (lane >> 4) & 1;
    const int brow = (lane & 7) + ((lane >> 4) & 1) * 8;
    const int bsel = (lane >> 3) & 1;
#pragma unroll
    for (int ks = 0; ks < 2; ks++) {
        uint32_t aaddr = smA + (rg * 32 + arow) * PITCH + ks * 32 + asel * 16;
        uint32_t baddr = smB + (cg * 64 + brow) * BPITCH + cc * 128 + ks * 32 + bsel * 16;
        uint32_t ah[2][4], al[2][4], bf[4][4];
        ldsm4(ah[0], aaddr);
        ldsm4(ah[1], aaddr + 16 * PITCH);
        ldsm4(al[0], aaddr + PLANE);
        ldsm4(al[1], aaddr + PLANE + 16 * PITCH);
#pragma unroll
        for (int t = 0; t < 4; t++) ldsm4(bf[t], baddr + t * 16 * BPITCH);
#pragma unroll
        for (int t = 0; t < 4; t++)
#pragma unroll
            for (int h = 0; h < 2; h++) {
                int nt = t * 2 + h;
                mma_f16(acc[0][nt], ah[0], bf[t][2 * h], bf[t][2 * h + 1]);
                mma_f16(acc[1][nt], ah[1], bf[t][2 * h], bf[t][2 * h + 1]);
                mma_f16(acc[0][nt], al[0], bf[t][2 * h], bf[t][2 * h + 1]);
                mma_f16(acc[1][nt], al[1], bf[t][2 * h], bf[t][2 * h + 1]);
            }
#pragma unroll
        for (int t = 0; t < 4; t++) ldsm4(bf[t], baddr + 64 + t * 16 * BPITCH);
#pragma unroll
        for (int t = 0; t < 4; t++)
#pragma unroll
            for (int h = 0; h < 2; h++) {
                int nt = t * 2 + h;
                mma_f16(acc[0][nt], ah[0], bf[t][2 * h], bf[t][2 * h + 1]);
                mma_f16(acc[1][nt], ah[1], bf[t][2 * h], bf[t][2 * h + 1]);
            }
    }
}

// ---------------------------------------------------------------------------
// Weight prepass: transpose [ci][co] -> [co][ci], split fp16 hi/lo interleaved
// ---------------------------------------------------------------------------
__global__ void prep_w_kernel(const float* __restrict__ W_res,
                              const float* __restrict__ W_out,
                              const float* __restrict__ Wf1,
                              const float* __restrict__ Wf2)
{
    __shared__ float t[32][33];
    const int b = blockIdx.x;
    const float* src;
    if (b < 162)       src = W_res + (size_t)b * C * C;
    else if (b < 189)  src = W_out + (size_t)(b - 162) * C * C;
    else if (b == 189) src = Wf1;
    else               src = Wf2;
    __half* dst = g_Wt + ((size_t)b << 15);

    const int j = threadIdx.x & 31, i0 = threadIdx.x >> 5;
    for (int tile = 0; tile < 16; tile++) {
        const int tr = tile >> 2, tc = tile & 3;
        __syncthreads();
#pragma unroll
        for (int p = 0; p < 4; p++)
            t[i0 + p * 8][j] = src[(tr * 32 + i0 + p * 8) * C + tc * 32 + j];
        __syncthreads();
#pragma unroll
        for (int p = 0; p < 4; p++) {
            int co = tc * 32 + i0 + p * 8;
            float w = t[j][i0 + p * 8];
            __half h, l; split2(w, h, l);
            size_t o = (size_t)co * 256 + tr * 64 + j;
            dst[o] = h;
            dst[o + 32] = l;
        }
    }
}

// ---------------------------------------------------------------------------
// Pair prepass (atomic-free)
// ---------------------------------------------------------------------------
__global__ __launch_bounds__(1024)
void count_scan_kernel(const int* __restrict__ nbr, int n)
{
    __shared__ int wsum[32];
    __shared__ int s_wk[NSEG * 32];
    const int tid = threadIdx.x, lane = tid & 31, wid = tid >> 5;
    const int m = blockIdx.x * 1024 + tid;

    unsigned valid27 = 0;
    if (m < n) {
        const int* np = nbr + (size_t)m * KNBR;
#pragma unroll
        for (int k = 0; k < KNBR; k++)
            if (k != 13 && np[k] >= 0) valid27 |= (1u << k);
    }
    int cnt = __popc(valid27);

#pragma unroll
    for (int k = 0; k < KNBR; k++) {
        if (k == 13) continue;
        unsigned ball = __ballot_sync(0xFFFFFFFFu, (valid27 >> k) & 1u);
        if (lane == 0) s_wk[k * 32 + wid] = __popc(ball);
    }

    int v = cnt;
#pragma unroll
    for (int o = 1; o < 32; o <<= 1) {
        int u = __shfl_up_sync(0xFFFFFFFFu, v, o);
        if (lane >= o) v += u;
    }
    if (lane == 31) wsum[wid] = v;
    __syncthreads();
    if (wid == 0) {
        int w = wsum[lane], iv = w;
#pragma unroll
        for (int o = 1; o < 32; o <<= 1) {
            int u = __shfl_up_sync(0xFFFFFFFFu, iv, o);
            if (lane >= o) iv += u;
        }
        wsum[lane] = iv - w;
    }
    __syncthreads();
    int pre = wsum[wid] + v - cnt;
    if (m < n) {
        g_mcnt[m] = (unsigned char)cnt;
        g_mbase[m] = pre;
    }
    if (tid == 1023) g_bsum[blockIdx.x] = pre + cnt;

    if (wid < NSEG && wid != 13) {
        int t = s_wk[wid * 32 + lane];
#pragma unroll
        for (int o = 16; o > 0; o >>= 1) t += __shfl_down_sync(0xFFFFFFFFu, t, o);
        if (lane == 0) g_kcnt[wid * NBMAX + blockIdx.x] = t;
    }
}

__global__ __launch_bounds__(1024)
void scan_bsum_kernel(int nb)
{
    __shared__ int s[512];
    const int tid = threadIdx.x, lane = tid & 31, w = tid >> 5;
    int v = 0;
    if (tid < 512) {
        v = (tid < nb) ? g_bsum[tid] : 0;
        s[tid] = v;
    }
    __syncthreads();
    for (int off = 1; off < 512; off <<= 1) {
        int u = (tid < 512 && tid >= off) ? s[tid - off] : 0;
        __syncthreads();
        if (tid < 512) s[tid] += u;
        __syncthreads();
    }
    if (tid < 512 && tid < nb) g_boff[tid] = s[tid] - v;

    // per-k exclusive scan over blocks — one warp per k, shuffle scan
    if (w < NSEG && w != 13) {
        int run = 0;
        for (int b0 = 0; b0 < nb; b0 += 32) {
            int b = b0 + lane;
            int x = (b < nb) ? g_kcnt[w * NBMAX + b] : 0;
            int inc = x;
#pragma unroll
            for (int o = 1; o < 32; o <<= 1) {
                int u = __shfl_up_sync(0xFFFFFFFFu, inc, o);
                if (lane >= o) inc += u;
            }
            if (b < nb) g_kbase[w * NBMAX + b] = run + inc - x;
            run += __shfl_sync(0xFFFFFFFFu, inc, 31);
        }
        if (lane == 0) g_cnt[w] = (unsigned)run;
    }
    if (tid == 0) g_cnt[13] = 0;
}

__global__ __launch_bounds__(1024)
void emit_pairs_kernel(const int* __restrict__ nbr, int n)
{
    __shared__ int s_wk[NSEG * 32];
    __shared__ int s_kb[NSEG];
    const int tid = threadIdx.x, lane = tid & 31, wid = tid >> 5;
    const int m = blockIdx.x * 1024 + tid;

    unsigned valid27 = 0;
    if (m < n) {
        const int* np = nbr + (size_t)m * KNBR;
#pragma unroll
        for (int k = 0; k < KNBR; k++)
            if (k != 13 && np[k] >= 0) valid27 |= (1u << k);
    }
#pragma unroll
    for (int k = 0; k < KNBR; k++) {
        if (k == 13) continue;
        unsigned ball = __ballot_sync(0xFFFFFFFFu, (valid27 >> k) & 1u);
        if (lane == 0) s_wk[k * 32 + wid] = __popc(ball);
    }
    if (tid < NSEG) s_kb[tid] = (tid != 13) ? g_kbase[tid * NBMAX + blockIdx.x] : 0;
    __syncthreads();

    if (wid < NSEG && wid != 13) {
        int v = s_wk[wid * 32 + lane], orig = v;
#pragma unroll
        for (int o = 1; o < 32; o <<= 1) {
            int u = __shfl_up_sync(0xFFFFFFFFu, v, o);
            if (lane >= o) v += u;
        }
        s_wk[wid * 32 + lane] = v - orig;
    }
    __syncthreads();

    int base = 0;
    if (m < n) base = g_boff[m >> 10] + g_mbase[m];
    const unsigned lt = (1u << lane) - 1u;
    int j = 0;
#pragma unroll
    for (int k = 0; k < KNBR; k++) {
        if (k == 13) continue;
        bool valid = (valid27 >> k) & 1u;
        unsigned ball = __ballot_sync(0xFFFFFFFFu, valid);
        if (valid) {
            int pos = s_kb[k] + s_wk[k * 32 + wid] + __popc(ball & lt);
            if (pos < CAP && base + j < SCR_ROWS) {
                g_pairg[k * CAP + pos] = nbr[(size_t)m * KNBR + k];
                g_slot[k * CAP + pos] = base + j;
            }
            j++;
        }
    }
    if (m < n) g_mbase[m] = base;
}

// ---------------------------------------------------------------------------
// Phase 1 (persistent, B-stationary, 2-stage, 2 CTA/SM): per-k pair GEMM
// -> fp32 scratch rows (m-sorted slots)
// ---------------------------------------------------------------------------
__global__ __launch_bounds__(256, 2)
void sparse_mma_p(const __half* __restrict__ in, const __half* __restrict__ WtLayer)
{
    const int k = blockIdx.x % NSEG;
    const int c = blockIdx.x / NSEG;
    unsigned cnt = g_cnt[k];
    if (cnt > CAP) cnt = CAP;
    const int ntk = (int)((cnt + TM - 1) / TM);
    const int mytiles = (ntk - c + PSP - 1) / PSP;
    if (mytiles <= 0) return;
    const int total = 4 * mytiles;

    extern __shared__ char smem[];
    const uint32_t sb = smem_u32(smem);
    const int tid = threadIdx.x, wid = tid >> 5, lane = tid & 31;
    const int lr = lane >> 2, lc = lane & 3;
    const int rg = wid & 3, cg = wid >> 2;

    int (*s_g)[TM] = (int(*)[TM])(smem + BFULL);
    int (*s_s)[TM] = (int(*)[TM])(smem + BFULL + 1024);
    const uint32_t ABASE = sb + BFULL + 2048;
    const __half* Wk = WtLayer + ((size_t)k << 15);

    auto load_idx = [&](int tl) {
        if (tid < TM) {
            int p = (c + tl * PSP) * TM + tid;
            int buf = tl & 1;
            s_g[buf][tid] = (p < (int)cnt) ? g_pairg[k * CAP + p] : -1;
            s_s[buf][tid] = (p < (int)cnt) ? g_slot[k * CAP + p] : -1;
        }
    };

    auto produce = [&](int jj) {
        const int tl = jj >> 2, cc = jj & 3, buf = tl & 1;
        const uint32_t stA = ABASE + (jj & 1) * ASZ;
#pragma unroll
        for (int i = 0; i < 4; i++) {
            int u = tid + 256 * i;
            int r = u >> 3, qq = u & 7;
            int idx = s_g[buf][r];
            const __half* src = in + (size_t)(idx < 0 ? 0 : idx) * 256 + cc * 64 + qq * 8;
            uint32_t dst = stA + ((qq & 4) ? PLANE : 0) + r * PITCH + (qq & 3) * 16;
            cp_async16_ca(dst, src, idx >= 0);
        }
        if (jj == 0) {
#pragma unroll
            for (int i = 0; i < 16; i++) {
                int u = tid + 256 * i;
                int r = u >> 5, q = u & 31;
                cp_async16_cg(sb + r * BPITCH + q * 16, Wk + (size_t)r * 256 + q * 8, true);
            }
        }
        CP_COMMIT();
    };

    float acc[2][8][4];
#pragma unroll
    for (int mt = 0; mt < 2; mt++)
#pragma unroll
        for (int nt = 0; nt < 8; nt++)
#pragma unroll
            for (int j = 0; j < 4; j++) acc[mt][nt][j] = 0.f;

    load_idx(0);
    __syncthreads();
    produce(0);
    if (total > 1) produce(1);

    for (int jj = 0; jj < total; jj++) {
        if (jj == total - 1) cp_wait<0>(); else cp_wait<1>();
        __syncthreads();
        gemm_chunk_p(ABASE + (jj & 1) * ASZ, sb, jj & 3, rg, cg, lane, acc);
        if ((jj & 3) == 0 && (jj >> 2) + 1 < mytiles) load_idx((jj >> 2) + 1);
        __syncthreads();
        if (jj + 2 < total) produce(jj + 2);

        if ((jj & 3) == 3) {
            const int tl = jj >> 2, buf = tl & 1;
            const int base = (c + tl * PSP) * TM;
#pragma unroll
            for (int mt = 0; mt < 2; mt++) {
#pragma unroll
                for (int hf = 0; hf < 2; hf++) {
                    int pr = rg * 32 + mt * 16 + hf * 8 + lr;
                    if (base + pr < (int)cnt) {
                        int slot = s_s[buf][pr];
                        if (slot >= 0) {
                            float* op = g_scr + (size_t)slot * C + cg * 64 + lc * 2;
#pragma unroll
                            for (int nt = 0; nt < 8; nt++)
                                *(float2*)(op + nt * 8) =
                                    make_float2(acc[mt][nt][hf * 2 + 0],
                                                acc[mt][nt][hf * 2 + 1]);
                        }
                    }
                }
            }
#pragma unroll
            for (int mt = 0; mt < 2; mt++)
#pragma unroll
                for (int nt = 0; nt < 8; nt++)
#pragma unroll
                    for (int j = 0; j < 4; j++) acc[mt][nt][j] = 0.f;
        }
    }
}

// ---------------------------------------------------------------------------
// Phase 2 (persistent, B-stationary, 2-stage, 2 CTA/SM): dense self-term GEMM
// + fused combine epilogue
// ---------------------------------------------------------------------------
__global__ __launch_bounds__(256, 2)
void dense_mma_p(const __half* __restrict__ in, __half* __restrict__ outAct,
                 const __half* __restrict__ Wk, const float* __restrict__ bias,
                 const __half* __restrict__ resid, int relu, int sparse,
                 int n, int ntiles)
{
    const int mytiles = (ntiles - (int)blockIdx.x + (int)gridDim.x - 1) / (int)gridDim.x;
    if (mytiles <= 0) return;
    const int total = 4 * mytiles;

    extern __shared__ char smem[];
    const uint32_t sb = smem_u32(smem);
    const int tid = threadIdx.x, wid = tid >> 5, lane = tid & 31;
    const int lr = lane >> 2, lc = lane & 3;
    const int rg = wid & 3, cg = wid >> 2;
    const uint32_t ABASE = sb + BFULL;

    auto produce = [&](int jj) {
        const int tl = jj >> 2, cc = jj & 3;
        const int row0 = ((int)blockIdx.x + tl * (int)gridDim.x) * TM;
        const uint32_t stA = ABASE + (jj & 1) * ASZ;
#pragma unroll
        for (int i = 0; i < 4; i++) {
            int u = tid + 256 * i;
            int r = u >> 3, qq = u & 7;
            int idx = (row0 + r < n) ? row0 + r : -1;
            const __half* src = in + (size_t)(idx < 0 ? 0 : idx) * 256 + cc * 64 + qq * 8;
            uint32_t dst = stA + ((qq & 4) ? PLANE : 0) + r * PITCH + (qq & 3) * 16;
            cp_async16_cg(dst, src, idx >= 0);
        }
        if (jj == 0) {
#pragma unroll
            for (int i = 0; i < 16; i++) {
                int u = tid + 256 * i;
                int r = u >> 5, q = u & 31;
                cp_async16_cg(sb + r * BPITCH + q * 16, Wk + (size_t)r * 256 + q * 8, true);
            }
        }
        CP_COMMIT();
    };

    float acc[2][8][4];
#pragma unroll
    for (int mt = 0; mt < 2; mt++)
#pragma unroll
        for (int nt = 0; nt < 8; nt++)
#pragma unroll
            for (int j = 0; j < 4; j++) acc[mt][nt][j] = 0.f;

    float2 bv[8];
#pragma unroll
    for (int nt = 0; nt < 8; nt++)
        bv[nt] = *(const float2*)(bias + cg * 64 + nt * 8 + lc * 2);

    produce(0);
    if (total > 1) produce(1);

    for (int jj = 0; jj < total; jj++) {
        if (jj == total - 1) cp_wait<0>(); else cp_wait<1>();
        __syncthreads();
        gemm_chunk_p(ABASE + (jj & 1) * ASZ, sb, jj & 3, rg, cg, lane, acc);
        __syncthreads();
        if (jj + 2 < total) produce(jj + 2);

        if ((jj & 3) == 3) {
            const int row0 = ((int)blockIdx.x + (jj >> 2) * (int)gridDim.x) * TM;
#pragma unroll
            for (int mt = 0; mt < 2; mt++) {
#pragma unroll
                for (int hf = 0; hf < 2; hf++) {
                    int row = row0 + rg * 32 + mt * 16 + hf * 8 + lr;
                    if (row >= n) continue;
                    float v[8][2];
#pragma unroll
                    for (int nt = 0; nt < 8; nt++) {
                        v[nt][0] = acc[mt][nt][hf * 2 + 0] + bv[nt].x;
                        v[nt][1] = acc[mt][nt][hf * 2 + 1] + bv[nt].y;
                    }
                    if (sparse) {
                        int basem = g_mbase[row];
                        int mc = g_mcnt[row];
                        const float* sp = g_scr + (size_t)basem * C + cg * 64 + lc * 2;
                        for (int j = 0; j < mc; j++) {
#pragma unroll
                            for (int nt = 0; nt < 8; nt++) {
                                float2 sv = *(const float2*)(sp + nt * 8);
                                v[nt][0] += sv.x;
                                v[nt][1] += sv.y;
                            }
                            sp += C;
                        }
                    }
#pragma unroll
                    for (int nt = 0; nt < 8; nt++) {
                        int col = cg * 64 + nt * 8 + lc * 2;
                        size_t o = (size_t)row * 256 + (col >> 5) * 64 + (col & 31);
                        float v0 = v[nt][0], v1 = v[nt][1];
                        if (resid) {
                            __half2 rh = *(const __half2*)(resid + o);
                            __half2 rl = *(const __half2*)(resid + o + 32);
                            v0 += __half2float(__low2half(rh)) + __half2float(__low2half(rl));
                            v1 += __half2float(__high2half(rh)) + __half2float(__high2half(rl));
                        }
                        if (relu) { v0 = fmaxf(v0, 0.f); v1 = fmaxf(v1, 0.f); }
                        __half h0, l0, h1, l1;
                        split2(v0, h0, l0);
                        split2(v1, h1, l1);
                        *(__half2*)(outAct + o)      = __halves2half2(h0, h1);
                        *(__half2*)(outAct + o + 32) = __halves2half2(l0, l1);
                    }
                }
            }
#pragma unroll
            for (int mt = 0; mt < 2; mt++)
#pragma unroll
                for (int nt = 0; nt < 8; nt++)
#pragma unroll
                    for (int j = 0; j < 4; j++) acc[mt][nt][j] = 0.f;
        }
    }
}

// ---------------------------------------------------------------------------
// Input layer (Cin = 1), sparsity-compacted
// ---------------------------------------------------------------------------
__global__ __launch_bounds__(256)
void layer_in_kernel(const float* __restrict__ x, __half* __restrict__ outAct,
                     const float* __restrict__ Win, const float* __restrict__ bin,
                     const int* __restrict__ nbr, int n)
{
    __shared__ float ws[KNBR][C];
    __shared__ float s_val[TM][28];
    __shared__ unsigned char s_kk[TM][28];
    __shared__ int s_cnt[TM];
    const int tid  = threadIdx.x;
    const int row0 = blockIdx.x * TM;

    for (int f = tid; f < KNBR * C; f += 256) ws[f / C][f & (C - 1)] = Win[f];
    if (tid < TM) {
        int row = row0 + tid;
        int j = 0;
        if (row < n) {
            const int* np = nbr + (size_t)row * KNBR;
#pragma unroll
            for (int k = 0; k < KNBR; k++) {
                int g = np[k];
                if (g >= 0) {
                    s_kk[tid][j] = (unsigned char)k;
                    s_val[tid][j] = x[g];
                    j++;
                }
            }
        }
        s_cnt[tid] = j;
    }
    __syncthreads();

    const int c  = tid & (C - 1);
    const int rg = tid >> 7;
    const float b = bin[c];
    const size_t co = (size_t)(c >> 5) * 64 + (c & 31);
    for (int r = rg; r < TM; r += 2) {
        int row = row0 + r;
        if (row >= n) continue;
        float acc = b;
        int cnt = s_cnt[r];
        for (int j = 0; j < cnt; j++)
            acc += s_val[r][j] * ws[s_kk[r][j]][c];
        acc = fmaxf(acc, 0.f);
        __half h, l; split2(acc, h, l);
        outAct[(size_t)row * 256 + co] = h;
        outAct[(size_t)row * 256 + co + 32] = l;
    }
}

// ---------------------------------------------------------------------------
// Final layer
// ---------------------------------------------------------------------------
__global__ __launch_bounds__(256)
void final_kernel(const __half* __restrict__ act, float* __restrict__ out,
                  const float* __restrict__ Wf3, const float* __restrict__ bf3, int n)
{
    __shared__ float hs[64][C + 1];
    __shared__ float wl[C * 3];
    __shared__ float bl[3];
    const int tid  = threadIdx.x;
    const int row0 = blockIdx.x * 64;

    for (int flat = tid; flat < 64 * C / 2; flat += 256) {
        int r = flat >> 6, q = flat & 63;
        int row = row0 + r;
        int col = (q >> 4) * 32 + (q & 15) * 2;
        float v0 = 0.f, v1 = 0.f;
        if (row < n) {
            size_t o = (size_t)row * 256 + (col >> 5) * 64 + (col & 31);
            __half2 rh = *(const __half2*)(act + o);
            __half2 rl = *(const __half2*)(act + o + 32);
            v0 = __half2float(__low2half(rh)) + __half2float(__low2half(rl));
            v1 = __half2float(__high2half(rh)) + __half2float(__high2half(rl));
        }
        hs[r][col] = v0;
        hs[r][col + 1] = v1;
    }
    for (int flat = tid; flat < C * 3; flat += 256) wl[flat] = Wf3[flat];
    if (tid < 3) bl[tid] = bf3[tid];
    __syncthreads();

    if (tid < 192) {
        int r = tid / 3, j = tid % 3;
        int row = row0 + r;
        if (row < n) {
            float acc = bl[j];
#pragma unroll 4
            for (int ci = 0; ci < C; ci++) acc += hs[r][ci] * wl[ci * 3 + j];
            out[(size_t)row * 3 + j] = acc;
        }
    }
}

// ---------------------------------------------------------------------------
extern "C" void kernel_launch(void* const* d_in, const int* in_sizes, int n_in,
                              void* d_out, int out_size)
{
    const float* x_feat = (const float*)d_in[0];
    const float* W_in   = (const float*)d_in[1];
    const float* b_in   = (const float*)d_in[2];
    const float* W_res  = (const float*)d_in[3];
    const float* b_res  = (const float*)d_in[4];
    const float* W_out  = (const float*)d_in[5];
    const float* b_out  = (const float*)d_in[6];
    const float* Wf1    = (const float*)d_in[7];
    const float* bf1    = (const float*)d_in[8];
    const float* Wf2    = (const float*)d_in[9];
    const float* bf2    = (const float*)d_in[10];
    const float* Wf3    = (const float*)d_in[11];
    const float* bf3    = (const float*)d_in[12];
    const int*   nbr    = (const int*)d_in[13];
    float* out = (float*)d_out;

    const int n = in_sizes[0];

    __half *actA, *actB, *Wt;
    cudaGetSymbolAddress((void**)&actA, g_actA);
    cudaGetSymbolAddress((void**)&actB, g_actB);
    cudaGetSymbolAddress((void**)&Wt, g_Wt);

    cudaFuncSetAttribute(sparse_mma_p, cudaFuncAttributeMaxDynamicSharedMemorySize, SP2_SMEM);
    cudaFuncSetAttribute(dense_mma_p, cudaFuncAttributeMaxDynamicSharedMemorySize, DN2_SMEM);

    const int ntiles = (n + TM - 1) / TM;
    const int gridM  = ntiles;
    const int gridD  = ntiles < GDMAX ? ntiles : GDMAX;
    const int gridS  = NSEG * PSP;
    const int nb     = (n + 1023) / 1024;

    prep_w_kernel<<<N_WMAT, 256>>>(W_res, W_out, Wf1, Wf2);
    count_scan_kernel<<<nb, 1024>>>(nbr, n);
    scan_bsum_kernel<<<1, 1024>>>(nb);
    emit_pairs_kernel<<<nb, 1024>>>(nbr, n);

    layer_in_kernel<<<gridM, 256>>>(x_feat, actA, W_in, b_in, nbr, n);

    for (int i = 0; i < 3; i++) {
        const __half* W0 = Wt + ((size_t)((i * 2 + 0) * KNBR) << 15);
        const __half* W1 = Wt + ((size_t)((i * 2 + 1) * KNBR) << 15);
        const float* b0 = b_res + (size_t)(i * 2 + 0) * C;
        const float* b1 = b_res + (size_t)(i * 2 + 1) * C;
        sparse_mma_p<<<gridS, 256, SP2_SMEM>>>(actA, W0);
        dense_mma_p<<<gridD, 256, DN2_SMEM>>>(actA, actB, W0 + ((size_t)13 << 15),
                                              b0, nullptr, 1, 1, n, ntiles);
        sparse_mma_p<<<gridS, 256, SP2_SMEM>>>(actB, W1);
        dense_mma_p<<<gridD, 256, DN2_SMEM>>>(actB, actA, W1 + ((size_t)13 << 15),
                                              b1, actA, 0, 1, n, ntiles);
    }

    const __half* Wo = Wt + ((size_t)(6 * KNBR) << 15);
    sparse_mma_p<<<gridS, 256, SP2_SMEM>>>(actA, Wo);
    dense_mma_p<<<gridD, 256, DN2_SMEM>>>(actA, actB, Wo + ((size_t)13 << 15),
                                          b_out, nullptr, 0, 1, n, ntiles);

    dense_mma_p<<<gridD, 256, DN2_SMEM>>>(actB, actA, Wt + ((size_t)189 << 15),
                                          bf1, nullptr, 1, 0, n, ntiles);
    dense_mma_p<<<gridD, 256, DN2_SMEM>>>(actA, actB, Wt + ((size_t)190 << 15),
                                          bf2, nullptr, 1, 0, n, ntiles);

    final_kernel<<<(n + 63) / 64, 256>>>(actB, out, Wf3, bf3, n);
}